// round 10
// baseline (speedup 1.0000x reference)
#include <cuda_runtime.h>
#include <cuda_fp16.h>
#include <math.h>

// B=4, C=2, H=W=1024, DS=4 -> 256x256, NUM_SEEDS=32, 15 steps, pool 7x7.
#define NCH   128
#define RS    97
#define PH    136             // halfs per row (272B) -> conflict-free LDS.128
#define PADC  8
#define ARRH  (RS * PH + 16)
#define SMEM_BYTES (3 * ARRH * 2)

__device__ float    g_road[4 * 256 * 256];
__device__ unsigned g_gtb[4 * 256 * 8];
__device__ int   g_sr[NCH];
__device__ int   g_sc[NCH];
__device__ int   g_scnt[NCH];
__device__ float g_sv[NCH];
__device__ float g_partial[NCH];
__device__ int   g_done;

__global__ void k_prep(const float* __restrict__ cls, const int* __restrict__ lab,
                       const float4* __restrict__ seeds) {
    if (blockIdx.x < 1024) {
        int idx = blockIdx.x * 256 + threadIdx.x;
        int j = idx & 255, i = (idx >> 8) & 255, b = idx >> 16;
        const float* c0 = cls + (size_t)(b * 2 + 0) * 1048576;
        const float* c1 = cls + (size_t)(b * 2 + 1) * 1048576;
        int r1 = 4 * i + 1, r2 = 4 * i + 2, cc = 4 * j;
        float4 a0 = *(const float4*)(c0 + r1 * 1024 + cc);
        float4 a1 = *(const float4*)(c1 + r1 * 1024 + cc);
        float4 b0 = *(const float4*)(c0 + r2 * 1024 + cc);
        float4 b1 = *(const float4*)(c1 + r2 * 1024 + cc);
        float p1 = 1.f / (1.f + expf(a0.y - a1.y));
        float p2 = 1.f / (1.f + expf(a0.z - a1.z));
        float p3 = 1.f / (1.f + expf(b0.y - b1.y));
        float p4 = 1.f / (1.f + expf(b0.z - b1.z));
        g_road[idx] = 0.25f * (p1 + p2 + p3 + p4);
        int g = lab[((size_t)b * 1024 + 4 * i) * 1024 + 4 * j];
        unsigned bits = __ballot_sync(0xffffffffu, g != 0);
        if ((threadIdx.x & 31) == 0)
            g_gtb[((size_t)b * 256 + i) * 8 + (j >> 5)] = bits;
    } else {
        const int n4 = (4 * 32 * 256 * 256) / 4;
        for (int i = (blockIdx.x - 1024) * 256 + threadIdx.x; i < n4; i += 1024 * 256) {
            float4 v = seeds[i];
            if (v.x > 0.f || v.y > 0.f || v.z > 0.f || v.w > 0.f) {
                float vals[4] = {v.x, v.y, v.z, v.w};
                #pragma unroll
                for (int k = 0; k < 4; k++) if (vals[k] > 0.f) {
                    int idx = i * 4 + k;
                    int ch = idx >> 16;
                    g_sr[ch] = (idx >> 8) & 255;
                    g_sc[ch] = idx & 255;
                    g_sv[ch] = vals[k];
                    g_scnt[ch] = 1;
                }
            }
        }
    }
}

__device__ __forceinline__ unsigned getword(const unsigned* row, int start) {
    int w = start >> 5;
    int sh = start & 31;
    unsigned lo = ((unsigned)w < 8u) ? row[w] : 0u;
    unsigned hi = ((unsigned)(w + 1) < 8u) ? row[w + 1] : 0u;
    return __funnelshift_r(lo, hi, sh);
}
__device__ __forceinline__ uint4 bshl(uint4 v, int s) {
    return make_uint4(v.x << s, __funnelshift_l(v.x, v.y, s),
                      __funnelshift_l(v.y, v.z, s), __funnelshift_l(v.z, v.w, s));
}
__device__ __forceinline__ uint4 bshr(uint4 v, int s) {
    return make_uint4(__funnelshift_r(v.x, v.y, s), __funnelshift_r(v.y, v.z, s),
                      __funnelshift_r(v.z, v.w, s), v.w >> s);
}
__device__ __forceinline__ uint4 bor(uint4 a, uint4 b) {
    return make_uint4(a.x | b.x, a.y | b.y, a.z | b.z, a.w | b.w);
}
__device__ __forceinline__ unsigned hmax2u(unsigned a, unsigned b) {
    __half2 r = __hmax2(*(__half2*)&a, *(__half2*)&b);
    return *(unsigned*)&r;
}
__device__ __forceinline__ unsigned hmin2u(unsigned a, unsigned b) {
    __half2 r = __hmin2(*(__half2*)&a, *(__half2*)&b);
    return *(unsigned*)&r;
}
__device__ __forceinline__ uint4 h8min(uint4 a, uint4 b) {
    return make_uint4(hmin2u(a.x, b.x), hmin2u(a.y, b.y),
                      hmin2u(a.z, b.z), hmin2u(a.w, b.w));
}

// Load 8 words (16 halfs: cols C-4..C+11) of row y: uint2 + uint4 + uint2.
__device__ __forceinline__ void load8(const __half* base, int y, int hoff, unsigned* w) {
    const __half* p = base + y * PH + hoff;
    uint2 l = *(const uint2*)(p - 4);
    uint4 m = *(const uint4*)(p);
    uint2 r = *(const uint2*)(p + 8);
    w[0] = l.x; w[1] = l.y; w[2] = m.x; w[3] = m.y;
    w[4] = m.z; w[5] = m.w; w[6] = r.x; w[7] = r.y;
}
__device__ __forceinline__ void acc8max(unsigned* a, const unsigned* b) {
    #pragma unroll
    for (int i = 0; i < 8; i++) a[i] = hmax2u(a[i], b[i]);
}
// Horizontal 7-max: w[0..7] = cols C-4..C+11 -> o[0..3] = cols C..C+7.
__device__ __forceinline__ void horiz7(const unsigned* w, unsigned* o) {
    unsigned a2[7];
    #pragma unroll
    for (int i = 0; i < 7; i++)
        a2[i] = hmax2u(w[i], __funnelshift_r(w[i], w[i + 1], 16));
    unsigned q4[6];
    #pragma unroll
    for (int i = 0; i < 6; i++)
        q4[i] = hmax2u(a2[i], a2[i + 1]);
    #pragma unroll
    for (int m = 0; m < 4; m++)
        o[m] = hmax2u(__funnelshift_r(q4[m], q4[m + 1], 16), q4[m + 2]);
}

// One channel per CTA, 1024 threads, 128 CTAs. One sync per iteration (fused 2D pool).
__global__ void __launch_bounds__(1024, 1) k_flood(float* __restrict__ out) {
    extern __shared__ __half smh[];
    __half* buf0 = smh;                 // ping
    __half* buf1 = smh + ARRH;          // pong (final result after 15 iters)
    __half* M    = smh + 2 * ARRH;
    __shared__ uint4 Gs[RS];
    __shared__ uint4 Gh[RS];
    __shared__ uint4 Gm[RS];
    __shared__ float wpart[32];
    __shared__ int   s_last;

    unsigned tid = threadIdx.x;
    int ch  = blockIdx.x;
    int b   = ch >> 5;
    const float c0log = -logf(1.0f - 1e-7f);

    bool hasseed = (g_scnt[ch] != 0);
    if (!hasseed) {
        if (tid == 0) g_partial[ch] = 65536.0f * c0log;
    } else {
        int sr = g_sr[ch], sc = g_sc[ch];
        float sv = g_sv[ch];
        int gr0 = sr - 48, gc0 = sc - 48;

        // ---- init: zero BOTH buffers and M; gt bits on top threads ----
        {
            uint4 z = make_uint4(0, 0, 0, 0);
            uint4* B0 = (uint4*)buf0;
            uint4* B1 = (uint4*)buf1;
            uint4* M8 = (uint4*)M;
            for (int i = tid; i < ARRH / 8; i += 1024) { B0[i] = z; B1[i] = z; M8[i] = z; }
        }
        if (tid >= 927) {
            int gy2 = tid - 927;               // 0..96
            int gy = gr0 + gy2;
            uint4 gm = make_uint4(0, 0, 0, 0);
            if ((unsigned)gy < 256u) {
                const unsigned* row = &g_gtb[((size_t)b * 256 + gy) * 8];
                gm.x = getword(row, gc0);
                gm.y = getword(row, gc0 + 32);
                gm.z = getword(row, gc0 + 64);
                gm.w = getword(row, gc0 + 96);
            }
            gm.w &= 1u;
            Gm[gy2] = gm;
            Gs[gy2] = make_uint4(0, 0, 0, 0);
        }
        __syncthreads();
        for (unsigned idx = tid; idx < RS * RS; idx += 1024) {
            unsigned y = idx / RS;
            unsigned x = idx - y * RS;
            int gy = gr0 + (int)y, gx = gc0 + (int)x;
            float m = 0.f;
            if ((unsigned)gy < 256u && (unsigned)gx < 256u)
                m = g_road[(b << 16) + (gy << 8) + gx];
            M[y * PH + PADC + x] = __float2half(m);
        }
        __syncthreads();
        if (tid == 0) {
            buf0[48 * PH + PADC + 48] = __float2half(sv);
            if (sv > 0.f) Gs[48].y |= (1u << 16);
        }
        __syncthreads();

        unsigned seedlo = (unsigned)__half_as_ushort(__float2half(sv));

        // ---- hoisted thread->unit mapping: 8-col group vj, 2-row band ----
        unsigned vj = tid % 13u;
        int y0off = (int)(tid / 13u) * 2;
        int hoff = PADC + ((int)vj << 3);
        bool v_seedcol = (vj == 6u);
        int gty = (int)tid - 927;

        #pragma unroll 1
        for (int it = 0; it < 15; it++) {
            const __half* S = (it & 1) ? buf1 : buf0;
            __half*       D = (it & 1) ? buf0 : buf1;
            int R  = 3 * (it + 1);             // <= 45
            int lo = 48 - R, hi = 48 + R;
            int jlo = lo >> 3, jhi = hi >> 3;
            int y0 = lo + y0off;

            if ((int)vj >= jlo && (int)vj <= jhi && y0 <= hi) {
                unsigned s0[8], t6[8], m1r[8], tmp[8];
                load8(S, y0 - 3, hoff, s0);        // row y0-3
                load8(S, y0 - 2, hoff, t6);        // t6 accumulates rows y0-2..y0+3
                #pragma unroll
                for (int r = -1; r <= 3; r++) { load8(S, y0 + r, hoff, tmp); acc8max(t6, tmp); }
                int r7 = y0 + 4 > 96 ? 96 : y0 + 4;
                load8(S, r7, hoff, m1r);           // row y0+4 (clamped; only for discarded rows)
                acc8max(s0, t6);                   // s0  = vmax rows y0-3..y0+3
                acc8max(m1r, t6);                  // m1r = vmax rows y0-2..y0+4
                {
                    unsigned o[4]; horiz7(s0, o);
                    uint4 val = make_uint4(o[0], o[1], o[2], o[3]);
                    val = h8min(val, *(const uint4*)(M + y0 * PH + hoff));
                    if (y0 == 48 && v_seedcol) val.x = hmax2u(val.x, seedlo);
                    *(uint4*)(D + y0 * PH + hoff) = val;
                }
                if (y0 + 1 <= hi) {
                    unsigned o[4]; horiz7(m1r, o);
                    uint4 val = make_uint4(o[0], o[1], o[2], o[3]);
                    val = h8min(val, *(const uint4*)(M + (y0 + 1) * PH + hoff));
                    if (y0 + 1 == 48 && v_seedcol) val.x = hmax2u(val.x, seedlo);
                    *(uint4*)(D + (y0 + 1) * PH + hoff) = val;
                }
            }
            // --- gt bitwise flood on float-idle warps 28-31 (internal named bar) ---
            if (tid >= 896) {
                if (gty >= 0) {
                    uint4 x = Gs[gty];
                    uint4 d = bor(x, bor(bshl(x, 1), bshr(x, 1)));
                    d = bor(d, bor(bshl(x, 2), bshr(x, 2)));
                    d = bor(d, bor(bshl(x, 3), bshr(x, 3)));
                    Gh[gty] = d;
                }
                asm volatile("bar.sync 1, 128;" ::: "memory");
                if (gty >= 0) {
                    int ym3 = gty - 3 < 0 ? 0 : gty - 3;
                    int yp3 = gty + 3 > 96 ? 96 : gty + 3;
                    uint4 acc = Gh[ym3];
                    for (int yy = ym3 + 1; yy <= yp3; yy++) acc = bor(acc, Gh[yy]);
                    acc.x &= Gm[gty].x; acc.y &= Gm[gty].y;
                    acc.z &= Gm[gty].z; acc.w &= Gm[gty].w;
                    if (gty == 48 && sv > 0.f) acc.y |= (1u << 16);
                    Gs[gty] = acc;
                }
            }
            __syncthreads();
        }

        // ---- fused BCE on buf1 (final): mantissa-product + exponent accumulation ----
        int ylo = 3 > -gr0 ? 3 : -gr0;
        int yhi = 93 < 255 - gr0 ? 93 : 255 - gr0;
        int xlo = 3 > -gc0 ? 3 : -gc0;
        int xhi = 93 < 255 - gc0 ? 93 : 255 - gc0;
        int nrows2 = yhi - ylo + 1;
        float pm = 1.0f;
        int   pe = 0;
        for (unsigned u = tid; u < (unsigned)nrows2 * 13u; u += 1024) {
            unsigned yy = u / 13u;
            unsigned g = u - yy * 13u;
            int y = ylo + (int)yy;
            int C = (int)(g << 3);
            if (C + 7 < xlo || C > xhi) continue;
            uint4 pv8 = *(const uint4*)(buf1 + y * PH + PADC + C);
            uint4 gw = Gs[y];
            float2 f[4];
            f[0] = __half22float2(*(__half2*)&pv8.x);
            f[1] = __half22float2(*(__half2*)&pv8.y);
            f[2] = __half22float2(*(__half2*)&pv8.z);
            f[3] = __half22float2(*(__half2*)&pv8.w);
            const float* fv = (const float*)f;
            #pragma unroll
            for (int k = 0; k < 8; k++) {
                int x = C + k;
                if (x >= xlo && x <= xhi) {
                    float p = fminf(fmaxf(fv[k], 1e-7f), 1.0f - 1e-7f);
                    int ws = x >> 5;
                    unsigned word = ws == 0 ? gw.x : ws == 1 ? gw.y : ws == 2 ? gw.z : gw.w;
                    float t = ((word >> (x & 31)) & 1u) ? p : (1.0f - p);
                    pm *= t;
                }
                if ((k & 3) == 3) {
                    int bi = __float_as_int(pm);
                    pe += (bi >> 23) - 127;
                    pm = __int_as_float((bi & 0x007fffff) | 0x3f800000);
                }
            }
        }
        float local = -(__logf(pm) + (float)pe * 0.69314718056f);

        #pragma unroll
        for (int off = 16; off; off >>= 1)
            local += __shfl_down_sync(0xffffffffu, local, off);
        if ((tid & 31) == 0) wpart[tid >> 5] = local;
        __syncthreads();
        if (tid == 0) {
            float s = 0.f;
            #pragma unroll
            for (int k = 0; k < 32; k++) s += wpart[k];
            float area = (float)((yhi - ylo + 1) * (xhi - xlo + 1));
            s += (65536.0f - area) * c0log;
            g_partial[ch] = s;
        }
    }

    // ---- last-block finalize ----
    if (tid == 0) {
        __threadfence();
        int old = atomicAdd(&g_done, 1);
        s_last = (old == NCH - 1);
    }
    __syncthreads();
    if (s_last && tid < 32) {
        float v = g_partial[tid] + g_partial[tid + 32] +
                  g_partial[tid + 64] + g_partial[tid + 96];
        #pragma unroll
        for (int off = 16; off; off >>= 1)
            v += __shfl_down_sync(0xffffffffu, v, off);
        if (tid == 0) {
            out[0] = 0.5f * v / 8388608.0f;
            g_done = 0;
        }
    }
}

extern "C" void kernel_launch(void* const* d_in, const int* in_sizes, int n_in,
                              void* d_out, int out_size) {
    const float* cls = (const float*)d_in[0];
    const int* lab   = (const int*)d_in[1];
    const float4* seeds = (const float4*)d_in[2];

    cudaFuncSetAttribute(k_flood, cudaFuncAttributeMaxDynamicSharedMemorySize, SMEM_BYTES);

    k_prep<<<2048, 256>>>(cls, lab, seeds);
    k_flood<<<128, 1024, SMEM_BYTES>>>((float*)d_out);
}

// round 11
// speedup vs baseline: 1.0018x; 1.0018x over previous
#include <cuda_runtime.h>
#include <cuda_fp16.h>
#include <math.h>

// B=4, C=2, H=W=1024, DS=4 -> 256x256, NUM_SEEDS=32, 15 steps, pool 7x7.
#define NCH   128
#define RS    97
#define PH    136             // halfs per row (272B) -> conflict-free LDS.128
#define PADC  8
#define ARRH  (RS * PH + 16)
#define SMEM_BYTES (3 * ARRH * 2)

__device__ __half   g_road[4 * 256 * 256];
__device__ unsigned g_gtb[4 * 256 * 8];
__device__ int      g_sr[NCH];
__device__ int      g_sc[NCH];
__device__ int      g_scnt[NCH];
__device__ float    g_sv[NCH];
__device__ float    g_partial[NCH];
__device__ unsigned g_arrive;       // monotonic grid barrier counter (never reset)
__device__ int      g_done;

__device__ __forceinline__ unsigned getword(const unsigned* row, int start) {
    int w = start >> 5;
    int sh = start & 31;
    unsigned lo = ((unsigned)w < 8u) ? row[w] : 0u;
    unsigned hi = ((unsigned)(w + 1) < 8u) ? row[w + 1] : 0u;
    return __funnelshift_r(lo, hi, sh);
}
__device__ __forceinline__ uint4 bshl(uint4 v, int s) {
    return make_uint4(v.x << s, __funnelshift_l(v.x, v.y, s),
                      __funnelshift_l(v.y, v.z, s), __funnelshift_l(v.z, v.w, s));
}
__device__ __forceinline__ uint4 bshr(uint4 v, int s) {
    return make_uint4(__funnelshift_r(v.x, v.y, s), __funnelshift_r(v.y, v.z, s),
                      __funnelshift_r(v.z, v.w, s), v.w >> s);
}
__device__ __forceinline__ uint4 bor(uint4 a, uint4 b) {
    return make_uint4(a.x | b.x, a.y | b.y, a.z | b.z, a.w | b.w);
}
__device__ __forceinline__ unsigned hmax2u(unsigned a, unsigned b) {
    __half2 r = __hmax2(*(__half2*)&a, *(__half2*)&b);
    return *(unsigned*)&r;
}
__device__ __forceinline__ unsigned hmin2u(unsigned a, unsigned b) {
    __half2 r = __hmin2(*(__half2*)&a, *(__half2*)&b);
    return *(unsigned*)&r;
}
__device__ __forceinline__ uint4 h8max(uint4 a, uint4 b) {
    return make_uint4(hmax2u(a.x, b.x), hmax2u(a.y, b.y),
                      hmax2u(a.z, b.z), hmax2u(a.w, b.w));
}
__device__ __forceinline__ uint4 h8min(uint4 a, uint4 b) {
    return make_uint4(hmin2u(a.x, b.x), hmin2u(a.y, b.y),
                      hmin2u(a.z, b.z), hmin2u(a.w, b.w));
}

// Single fused kernel: 128 CTAs x 1024 threads, all co-resident (grid <= SM count).
__global__ void __launch_bounds__(1024, 1) k_all(const float* __restrict__ cls,
                                                 const int* __restrict__ lab,
                                                 const float4* __restrict__ seeds,
                                                 float* __restrict__ out) {
    extern __shared__ __half smh[];
    __half* A  = smh;
    __half* Bt = smh + ARRH;
    __half* M  = smh + 2 * ARRH;
    __shared__ uint4 Gs[RS];
    __shared__ uint4 Gh[RS];
    __shared__ uint4 Gm[RS];
    __shared__ float wpart[32];
    __shared__ int   s_last;

    unsigned tid = threadIdx.x;
    int ch  = blockIdx.x;
    int b   = ch >> 5;
    const float c0log = -logf(1.0f - 1e-7f);

    // ================= phase 0: this CTA's 1/128 share of prep =================
    // masks + gt bits: 262144 pixels over 131072 threads (2 iters)
    for (unsigned idx = blockIdx.x * 1024u + tid; idx < 262144u; idx += 131072u) {
        int j = idx & 255, i = (idx >> 8) & 255, bb = idx >> 16;
        const float* c0 = cls + (size_t)(bb * 2 + 0) * 1048576;
        const float* c1 = cls + (size_t)(bb * 2 + 1) * 1048576;
        int r1 = 4 * i + 1, r2 = 4 * i + 2, cc = 4 * j;
        float4 a0 = *(const float4*)(c0 + r1 * 1024 + cc);
        float4 a1 = *(const float4*)(c1 + r1 * 1024 + cc);
        float4 b0 = *(const float4*)(c0 + r2 * 1024 + cc);
        float4 b1 = *(const float4*)(c1 + r2 * 1024 + cc);
        float p1 = 1.f / (1.f + expf(a0.y - a1.y));
        float p2 = 1.f / (1.f + expf(a0.z - a1.z));
        float p3 = 1.f / (1.f + expf(b0.y - b1.y));
        float p4 = 1.f / (1.f + expf(b0.z - b1.z));
        g_road[idx] = __float2half(0.25f * (p1 + p2 + p3 + p4));
        int g = lab[((size_t)bb * 1024 + 4 * i) * 1024 + 4 * j];
        unsigned bits = __ballot_sync(0xffffffffu, g != 0);
        if ((tid & 31) == 0)
            g_gtb[((size_t)bb * 256 + i) * 8 + (j >> 5)] = bits;
    }
    // seed scan: 2097152 float4s over 131072 threads (16 iters)
    for (unsigned i = blockIdx.x * 1024u + tid; i < 2097152u; i += 131072u) {
        float4 v = seeds[i];
        if (v.x > 0.f || v.y > 0.f || v.z > 0.f || v.w > 0.f) {
            float vals[4] = {v.x, v.y, v.z, v.w};
            #pragma unroll
            for (int k = 0; k < 4; k++) if (vals[k] > 0.f) {
                int idx = i * 4 + k;
                int cch = idx >> 16;
                g_sr[cch] = (idx >> 8) & 255;
                g_sc[cch] = idx & 255;
                g_sv[cch] = vals[k];
                g_scnt[cch] = 1;
            }
        }
    }
    // zero local smem while waiting is cheap; do it before arrival
    {
        uint4 z = make_uint4(0, 0, 0, 0);
        uint4* A8 = (uint4*)A;
        uint4* M8 = (uint4*)M;
        for (int i = tid; i < ARRH / 8; i += 1024) { A8[i] = z; M8[i] = z; }
    }

    // ================= grid-wide barrier (all 128 CTAs co-resident) =================
    __threadfence();
    __syncthreads();
    if (tid == 0) {
        unsigned old = atomicAdd(&g_arrive, 1u);
        unsigned target = (old / 128u + 1u) * 128u;
        while (*(volatile unsigned*)&g_arrive < target) { }
    }
    __syncthreads();
    __threadfence();

    // ================= phase 1: flood (R8 body) =================
    bool hasseed = (g_scnt[ch] != 0);
    if (!hasseed) {
        if (tid == 0) g_partial[ch] = 65536.0f * c0log;
    } else {
        int sr = g_sr[ch], sc = g_sc[ch];
        float sv = g_sv[ch];
        int gr0 = sr - 48, gc0 = sc - 48;

        if (tid >= 927) {
            int gy2 = tid - 927;               // 0..96
            int gy = gr0 + gy2;
            uint4 gm = make_uint4(0, 0, 0, 0);
            if ((unsigned)gy < 256u) {
                const unsigned* row = &g_gtb[((size_t)b * 256 + gy) * 8];
                gm.x = getword(row, gc0);
                gm.y = getword(row, gc0 + 32);
                gm.z = getword(row, gc0 + 64);
                gm.w = getword(row, gc0 + 96);
            }
            gm.w &= 1u;
            Gm[gy2] = gm;
            Gs[gy2] = make_uint4(0, 0, 0, 0);
        }
        for (unsigned idx = tid; idx < RS * RS; idx += 1024) {
            unsigned y = idx / RS;
            unsigned x = idx - y * RS;
            int gy = gr0 + (int)y, gx = gc0 + (int)x;
            __half m = __ushort_as_half((unsigned short)0);
            if ((unsigned)gy < 256u && (unsigned)gx < 256u)
                m = g_road[(b << 16) + (gy << 8) + gx];
            M[y * PH + PADC + x] = m;
        }
        __syncthreads();
        if (tid == 0) {
            A[48 * PH + PADC + 48] = __float2half(sv);
            if (sv > 0.f) Gs[48].y |= (1u << 16);
        }
        __syncthreads();

        unsigned seedlo = (unsigned)__half_as_ushort(__float2half(sv));

        for (int it = 0; it < 15; it++) {
            int R   = 3 * (it + 1);                // <= 45
            int lo  = 48 - R, hi = 48 + R;
            int rlo = lo - 3, rhi = hi + 3;        // within [0,96]
            int jlo = lo >> 3, jhi = hi >> 3;
            int btlo = jlo << 3, bthi = (jhi << 3) + 7;

            // --- horizontal 7-max (half2, 16-output units): A -> Bt ---
            {
                unsigned g = tid / 97u;            // col group (16 cols); 0..6 active
                int y = (int)(tid - g * 97u);
                int X = (int)(g << 4);
                if (g < 7 && y >= rlo && y <= rhi && X <= bthi && X + 15 >= btlo) {
                    const uint4* src = (const uint4*)(A + y * PH + X);  // cols X-8..X+23
                    uint4 t0 = src[0], t1 = src[1], t2 = src[2], t3 = src[3];
                    unsigned v[16] = {t0.x, t0.y, t0.z, t0.w, t1.x, t1.y, t1.z, t1.w,
                                      t2.x, t2.y, t2.z, t2.w, t3.x, t3.y, t3.z, t3.w};
                    unsigned a2[13];
                    #pragma unroll
                    for (int j2 = 0; j2 < 13; j2++)
                        a2[j2] = hmax2u(v[j2], __funnelshift_r(v[j2], v[j2 + 1], 16));
                    unsigned q4[12];
                    #pragma unroll
                    for (int j2 = 0; j2 < 12; j2++)
                        q4[j2] = hmax2u(a2[j2], a2[j2 + 1]);
                    unsigned o[8];
                    #pragma unroll
                    for (int m2 = 0; m2 < 8; m2++)
                        o[m2] = hmax2u(__funnelshift_r(q4[m2 + 2], q4[m2 + 3], 16),
                                       q4[m2 + 4]);
                    uint4* dst = (uint4*)(Bt + y * PH + PADC + X);
                    dst[0] = make_uint4(o[0], o[1], o[2], o[3]);
                    dst[1] = make_uint4(o[4], o[5], o[6], o[7]);
                }
            }
            // --- gt bitwise horizontal dilate ---
            if (tid >= 927) {
                int gy2 = tid - 927;
                uint4 x = Gs[gy2];
                uint4 d = bor(x, bor(bshl(x, 1), bshr(x, 1)));
                d = bor(d, bor(bshl(x, 2), bshr(x, 2)));
                d = bor(d, bor(bshl(x, 3), bshr(x, 3)));
                Gh[gy2] = d;
            }
            __syncthreads();

            // --- vertical 7-max (3-row bands, 8-col groups) + min(mask) + seed ---
            {
                unsigned j = tid % 13u;
                unsigned band = tid / 13u;
                int y0 = lo + (int)band * 3;
                if ((int)j >= jlo && (int)j <= jhi && y0 <= hi) {
                    int hoff = PADC + ((int)j << 3);
                    uint4 t = *(const uint4*)(Bt + (y0 - 1) * PH + hoff);
                    #pragma unroll
                    for (int i = 0; i < 4; i++)
                        t = h8max(t, *(const uint4*)(Bt + (y0 + i) * PH + hoff));
                    uint4 rA = *(const uint4*)(Bt + (y0 - 3) * PH + hoff);
                    uint4 rB = *(const uint4*)(Bt + (y0 - 2) * PH + hoff);
                    int r4 = y0 + 4 > rhi ? rhi : y0 + 4;
                    int r5 = y0 + 5 > rhi ? rhi : y0 + 5;
                    uint4 rC = *(const uint4*)(Bt + r4 * PH + hoff);
                    uint4 rD = *(const uint4*)(Bt + r5 * PH + hoff);
                    uint4 m0 = h8max(t, h8max(rA, rB));
                    uint4 m1 = h8max(t, h8max(rB, rC));
                    uint4 m2 = h8max(t, h8max(rC, rD));
                    uint4 val0 = h8min(m0, *(const uint4*)(M + y0 * PH + hoff));
                    if (y0 == 48 && j == 6u) val0.x = hmax2u(val0.x, seedlo);
                    *(uint4*)(A + y0 * PH + hoff) = val0;
                    if (y0 + 1 <= hi) {
                        uint4 val1 = h8min(m1, *(const uint4*)(M + (y0 + 1) * PH + hoff));
                        if (y0 + 1 == 48 && j == 6u) val1.x = hmax2u(val1.x, seedlo);
                        *(uint4*)(A + (y0 + 1) * PH + hoff) = val1;
                    }
                    if (y0 + 2 <= hi) {
                        uint4 val2 = h8min(m2, *(const uint4*)(M + (y0 + 2) * PH + hoff));
                        if (y0 + 2 == 48 && j == 6u) val2.x = hmax2u(val2.x, seedlo);
                        *(uint4*)(A + (y0 + 2) * PH + hoff) = val2;
                    }
                }
            }
            // --- gt bitwise vertical dilate + AND mask + seed ---
            if (tid >= 927) {
                int y = tid - 927;
                int ym3 = y - 3 < 0 ? 0 : y - 3;
                int yp3 = y + 3 > 96 ? 96 : y + 3;
                uint4 acc = Gh[ym3];
                for (int yy = ym3 + 1; yy <= yp3; yy++) acc = bor(acc, Gh[yy]);
                acc.x &= Gm[y].x; acc.y &= Gm[y].y; acc.z &= Gm[y].z; acc.w &= Gm[y].w;
                if (y == 48 && sv > 0.f) acc.y |= (1u << 16);
                Gs[y] = acc;
            }
            __syncthreads();
        }

        // ---- fused BCE: mantissa-product + exponent accumulation ----
        int ylo = 3 > -gr0 ? 3 : -gr0;
        int yhi = 93 < 255 - gr0 ? 93 : 255 - gr0;
        int xlo = 3 > -gc0 ? 3 : -gc0;
        int xhi = 93 < 255 - gc0 ? 93 : 255 - gc0;
        int nrows2 = yhi - ylo + 1;
        float pm = 1.0f;
        int   pe = 0;
        for (unsigned u = tid; u < (unsigned)nrows2 * 13u; u += 1024) {
            unsigned yy = u / 13u;
            unsigned g = u - yy * 13u;
            int y = ylo + (int)yy;
            int C = (int)(g << 3);
            if (C + 7 < xlo || C > xhi) continue;
            uint4 pv8 = *(const uint4*)(A + y * PH + PADC + C);
            uint4 gw = Gs[y];
            float2 f[4];
            f[0] = __half22float2(*(__half2*)&pv8.x);
            f[1] = __half22float2(*(__half2*)&pv8.y);
            f[2] = __half22float2(*(__half2*)&pv8.z);
            f[3] = __half22float2(*(__half2*)&pv8.w);
            const float* fv = (const float*)f;
            #pragma unroll
            for (int k = 0; k < 8; k++) {
                int x = C + k;
                if (x >= xlo && x <= xhi) {
                    float p = fminf(fmaxf(fv[k], 1e-7f), 1.0f - 1e-7f);
                    int ws = x >> 5;
                    unsigned word = ws == 0 ? gw.x : ws == 1 ? gw.y : ws == 2 ? gw.z : gw.w;
                    float t = ((word >> (x & 31)) & 1u) ? p : (1.0f - p);
                    pm *= t;
                }
                if ((k & 3) == 3) {
                    int bi = __float_as_int(pm);
                    pe += (bi >> 23) - 127;
                    pm = __int_as_float((bi & 0x007fffff) | 0x3f800000);
                }
            }
        }
        float local = -(__logf(pm) + (float)pe * 0.69314718056f);

        #pragma unroll
        for (int off = 16; off; off >>= 1)
            local += __shfl_down_sync(0xffffffffu, local, off);
        if ((tid & 31) == 0) wpart[tid >> 5] = local;
        __syncthreads();
        if (tid == 0) {
            float s = 0.f;
            #pragma unroll
            for (int k = 0; k < 32; k++) s += wpart[k];
            float area = (float)((yhi - ylo + 1) * (xhi - xlo + 1));
            s += (65536.0f - area) * c0log;
            g_partial[ch] = s;
        }
    }

    // ---- last-block finalize ----
    if (tid == 0) {
        __threadfence();
        int old = atomicAdd(&g_done, 1);
        s_last = (old == NCH - 1);
    }
    __syncthreads();
    if (s_last && tid < 32) {
        float v = g_partial[tid] + g_partial[tid + 32] +
                  g_partial[tid + 64] + g_partial[tid + 96];
        #pragma unroll
        for (int off = 16; off; off >>= 1)
            v += __shfl_down_sync(0xffffffffu, v, off);
        if (tid == 0) {
            out[0] = 0.5f * v / 8388608.0f;
            g_done = 0;
        }
    }
}

extern "C" void kernel_launch(void* const* d_in, const int* in_sizes, int n_in,
                              void* d_out, int out_size) {
    const float* cls = (const float*)d_in[0];
    const int* lab   = (const int*)d_in[1];
    const float4* seeds = (const float4*)d_in[2];

    cudaFuncSetAttribute(k_all, cudaFuncAttributeMaxDynamicSharedMemorySize, SMEM_BYTES);

    k_all<<<128, 1024, SMEM_BYTES>>>(cls, lab, seeds, (float*)d_out);
}

// round 12
// speedup vs baseline: 1.0729x; 1.0709x over previous
#include <cuda_runtime.h>
#include <cuda_fp16.h>
#include <math.h>

// B=4, C=2, H=W=1024, DS=4 -> 256x256, NUM_SEEDS=32, 15 steps, pool 7x7.
#define NCH   128
#define RS    97
#define PH    136             // halfs per row (272B) -> conflict-free LDS.128
#define PADC  8
#define ARRH  (RS * PH + 16)
#define SMEM_BYTES (3 * ARRH * 2)

__device__ float    g_road[4 * 256 * 256];
__device__ unsigned g_gtb[4 * 256 * 8];
__device__ int   g_sr[NCH];
__device__ int   g_sc[NCH];
__device__ int   g_scnt[NCH];
__device__ float g_sv[NCH];
__device__ float g_partial[NCH];
__device__ int   g_done;

__global__ void k_prep(const float* __restrict__ cls, const int* __restrict__ lab,
                       const float4* __restrict__ seeds) {
    // blocks [0,1024): downsampled road prob + gt bits (1 unit each)
    if (blockIdx.x < 1024) {
        int idx = blockIdx.x * 256 + threadIdx.x;
        int j = idx & 255, i = (idx >> 8) & 255, b = idx >> 16;
        const float* c0 = cls + (size_t)(b * 2 + 0) * 1048576;
        const float* c1 = cls + (size_t)(b * 2 + 1) * 1048576;
        int r1 = 4 * i + 1, r2 = 4 * i + 2, cc = 4 * j;
        float4 a0 = *(const float4*)(c0 + r1 * 1024 + cc);
        float4 a1 = *(const float4*)(c1 + r1 * 1024 + cc);
        float4 b0 = *(const float4*)(c0 + r2 * 1024 + cc);
        float4 b1 = *(const float4*)(c1 + r2 * 1024 + cc);
        float p1 = 1.f / (1.f + expf(a0.y - a1.y));
        float p2 = 1.f / (1.f + expf(a0.z - a1.z));
        float p3 = 1.f / (1.f + expf(b0.y - b1.y));
        float p4 = 1.f / (1.f + expf(b0.z - b1.z));
        g_road[idx] = 0.25f * (p1 + p2 + p3 + p4);
        int g = lab[((size_t)b * 1024 + 4 * i) * 1024 + 4 * j];
        unsigned bits = __ballot_sync(0xffffffffu, g != 0);
        if ((threadIdx.x & 31) == 0)
            g_gtb[((size_t)b * 256 + i) * 8 + (j >> 5)] = bits;
    }
    // ALL 2048 blocks share the seed scan (4 units each) — balances with mask blocks
    {
        const unsigned n4 = (4 * 32 * 256 * 256) / 4;
        for (unsigned i = blockIdx.x * 256u + threadIdx.x; i < n4; i += 2048u * 256u) {
            float4 v = seeds[i];
            if (v.x > 0.f || v.y > 0.f || v.z > 0.f || v.w > 0.f) {
                float vals[4] = {v.x, v.y, v.z, v.w};
                #pragma unroll
                for (int k = 0; k < 4; k++) if (vals[k] > 0.f) {
                    unsigned idx = i * 4u + k;
                    int ch = idx >> 16;
                    g_sr[ch] = (idx >> 8) & 255;
                    g_sc[ch] = idx & 255;
                    g_sv[ch] = vals[k];
                    g_scnt[ch] = 1;
                }
            }
        }
    }
    // allow the dependent flood kernel's CTAs to launch (PDL)
    asm volatile("griddepcontrol.launch_dependents;" ::: "memory");
}

__device__ __forceinline__ unsigned getword(const unsigned* row, int start) {
    int w = start >> 5;
    int sh = start & 31;
    unsigned lo = ((unsigned)w < 8u) ? row[w] : 0u;
    unsigned hi = ((unsigned)(w + 1) < 8u) ? row[w + 1] : 0u;
    return __funnelshift_r(lo, hi, sh);
}
__device__ __forceinline__ uint4 bshl(uint4 v, int s) {
    return make_uint4(v.x << s, __funnelshift_l(v.x, v.y, s),
                      __funnelshift_l(v.y, v.z, s), __funnelshift_l(v.z, v.w, s));
}
__device__ __forceinline__ uint4 bshr(uint4 v, int s) {
    return make_uint4(__funnelshift_r(v.x, v.y, s), __funnelshift_r(v.y, v.z, s),
                      __funnelshift_r(v.z, v.w, s), v.w >> s);
}
__device__ __forceinline__ uint4 bor(uint4 a, uint4 b) {
    return make_uint4(a.x | b.x, a.y | b.y, a.z | b.z, a.w | b.w);
}
__device__ __forceinline__ unsigned hmax2u(unsigned a, unsigned b) {
    __half2 r = __hmax2(*(__half2*)&a, *(__half2*)&b);
    return *(unsigned*)&r;
}
__device__ __forceinline__ unsigned hmin2u(unsigned a, unsigned b) {
    __half2 r = __hmin2(*(__half2*)&a, *(__half2*)&b);
    return *(unsigned*)&r;
}
__device__ __forceinline__ uint4 h8max(uint4 a, uint4 b) {
    return make_uint4(hmax2u(a.x, b.x), hmax2u(a.y, b.y),
                      hmax2u(a.z, b.z), hmax2u(a.w, b.w));
}
__device__ __forceinline__ uint4 h8min(uint4 a, uint4 b) {
    return make_uint4(hmin2u(a.x, b.x), hmin2u(a.y, b.y),
                      hmin2u(a.z, b.z), hmin2u(a.w, b.w));
}

// One channel per CTA, 1024 threads, 128 CTAs (full chip).
__global__ void __launch_bounds__(1024, 1) k_flood(float* __restrict__ out) {
    extern __shared__ __half smh[];
    __half* A  = smh;
    __half* Bt = smh + ARRH;
    __half* M  = smh + 2 * ARRH;
    __shared__ uint4 Gs[RS];
    __shared__ uint4 Gh[RS];
    __shared__ uint4 Gm[RS];
    __shared__ float wpart[32];
    __shared__ int   s_last;

    unsigned tid = threadIdx.x;
    int ch  = blockIdx.x;
    int b   = ch >> 5;
    const float c0log = -logf(1.0f - 1e-7f);

    // ---- pre-dependency work: zero A and M while k_prep finishes (PDL overlap) ----
    {
        uint4 z = make_uint4(0, 0, 0, 0);
        uint4* A8 = (uint4*)A;
        uint4* M8 = (uint4*)M;
        for (int i = tid; i < ARRH / 8; i += 1024) { A8[i] = z; M8[i] = z; }
    }
    // wait for k_prep's writes to be visible
    asm volatile("griddepcontrol.wait;" ::: "memory");
    __syncthreads();

    bool hasseed = (g_scnt[ch] != 0);
    if (!hasseed) {
        if (tid == 0) g_partial[ch] = 65536.0f * c0log;
    } else {
        int sr = g_sr[ch], sc = g_sc[ch];
        float sv = g_sv[ch];
        int gr0 = sr - 48, gc0 = sc - 48;

        if (tid >= 927) {
            int gy2 = tid - 927;               // 0..96
            int gy = gr0 + gy2;
            uint4 gm = make_uint4(0, 0, 0, 0);
            if ((unsigned)gy < 256u) {
                const unsigned* row = &g_gtb[((size_t)b * 256 + gy) * 8];
                gm.x = getword(row, gc0);
                gm.y = getword(row, gc0 + 32);
                gm.z = getword(row, gc0 + 64);
                gm.w = getword(row, gc0 + 96);
            }
            gm.w &= 1u;
            Gm[gy2] = gm;
            Gs[gy2] = make_uint4(0, 0, 0, 0);
        }
        for (unsigned idx = tid; idx < RS * RS; idx += 1024) {
            unsigned y = idx / RS;
            unsigned x = idx - y * RS;
            int gy = gr0 + (int)y, gx = gc0 + (int)x;
            float m = 0.f;
            if ((unsigned)gy < 256u && (unsigned)gx < 256u)
                m = g_road[(b << 16) + (gy << 8) + gx];
            M[y * PH + PADC + x] = __float2half(m);
        }
        __syncthreads();
        if (tid == 0) {
            A[48 * PH + PADC + 48] = __float2half(sv);
            if (sv > 0.f) Gs[48].y |= (1u << 16);
        }
        __syncthreads();

        unsigned seedlo = (unsigned)__half_as_ushort(__float2half(sv));

        for (int it = 0; it < 15; it++) {
            int R   = 3 * (it + 1);                // <= 45
            int lo  = 48 - R, hi = 48 + R;
            int rlo = lo - 3, rhi = hi + 3;        // within [0,96]
            int jlo = lo >> 3, jhi = hi >> 3;
            int btlo = jlo << 3, bthi = (jhi << 3) + 7;

            // --- horizontal 7-max (half2, 16-output units): A -> Bt ---
            {
                unsigned g = tid / 97u;            // col group (16 cols); 0..6 active
                int y = (int)(tid - g * 97u);
                int X = (int)(g << 4);
                if (g < 7 && y >= rlo && y <= rhi && X <= bthi && X + 15 >= btlo) {
                    const uint4* src = (const uint4*)(A + y * PH + X);  // cols X-8..X+23
                    uint4 t0 = src[0], t1 = src[1], t2 = src[2], t3 = src[3];
                    unsigned v[16] = {t0.x, t0.y, t0.z, t0.w, t1.x, t1.y, t1.z, t1.w,
                                      t2.x, t2.y, t2.z, t2.w, t3.x, t3.y, t3.z, t3.w};
                    unsigned a2[13];
                    #pragma unroll
                    for (int j2 = 0; j2 < 13; j2++)
                        a2[j2] = hmax2u(v[j2], __funnelshift_r(v[j2], v[j2 + 1], 16));
                    unsigned q4[12];
                    #pragma unroll
                    for (int j2 = 0; j2 < 12; j2++)
                        q4[j2] = hmax2u(a2[j2], a2[j2 + 1]);
                    unsigned o[8];
                    #pragma unroll
                    for (int m2 = 0; m2 < 8; m2++)
                        o[m2] = hmax2u(__funnelshift_r(q4[m2 + 2], q4[m2 + 3], 16),
                                       q4[m2 + 4]);
                    uint4* dst = (uint4*)(Bt + y * PH + PADC + X);
                    dst[0] = make_uint4(o[0], o[1], o[2], o[3]);
                    dst[1] = make_uint4(o[4], o[5], o[6], o[7]);
                }
            }
            // --- gt bitwise horizontal dilate ---
            if (tid >= 927) {
                int gy2 = tid - 927;
                uint4 x = Gs[gy2];
                uint4 d = bor(x, bor(bshl(x, 1), bshr(x, 1)));
                d = bor(d, bor(bshl(x, 2), bshr(x, 2)));
                d = bor(d, bor(bshl(x, 3), bshr(x, 3)));
                Gh[gy2] = d;
            }
            __syncthreads();

            // --- vertical 7-max (3-row bands, 8-col groups) + min(mask) + seed ---
            {
                unsigned j = tid % 13u;
                unsigned band = tid / 13u;
                int y0 = lo + (int)band * 3;
                if ((int)j >= jlo && (int)j <= jhi && y0 <= hi) {
                    int hoff = PADC + ((int)j << 3);
                    uint4 t = *(const uint4*)(Bt + (y0 - 1) * PH + hoff);
                    #pragma unroll
                    for (int i = 0; i < 4; i++)
                        t = h8max(t, *(const uint4*)(Bt + (y0 + i) * PH + hoff));
                    uint4 rA = *(const uint4*)(Bt + (y0 - 3) * PH + hoff);
                    uint4 rB = *(const uint4*)(Bt + (y0 - 2) * PH + hoff);
                    int r4 = y0 + 4 > rhi ? rhi : y0 + 4;
                    int r5 = y0 + 5 > rhi ? rhi : y0 + 5;
                    uint4 rC = *(const uint4*)(Bt + r4 * PH + hoff);
                    uint4 rD = *(const uint4*)(Bt + r5 * PH + hoff);
                    uint4 m0 = h8max(t, h8max(rA, rB));
                    uint4 m1 = h8max(t, h8max(rB, rC));
                    uint4 m2 = h8max(t, h8max(rC, rD));
                    uint4 val0 = h8min(m0, *(const uint4*)(M + y0 * PH + hoff));
                    if (y0 == 48 && j == 6u) val0.x = hmax2u(val0.x, seedlo);
                    *(uint4*)(A + y0 * PH + hoff) = val0;
                    if (y0 + 1 <= hi) {
                        uint4 val1 = h8min(m1, *(const uint4*)(M + (y0 + 1) * PH + hoff));
                        if (y0 + 1 == 48 && j == 6u) val1.x = hmax2u(val1.x, seedlo);
                        *(uint4*)(A + (y0 + 1) * PH + hoff) = val1;
                    }
                    if (y0 + 2 <= hi) {
                        uint4 val2 = h8min(m2, *(const uint4*)(M + (y0 + 2) * PH + hoff));
                        if (y0 + 2 == 48 && j == 6u) val2.x = hmax2u(val2.x, seedlo);
                        *(uint4*)(A + (y0 + 2) * PH + hoff) = val2;
                    }
                }
            }
            // --- gt bitwise vertical dilate + AND mask + seed ---
            if (tid >= 927) {
                int y = tid - 927;
                int ym3 = y - 3 < 0 ? 0 : y - 3;
                int yp3 = y + 3 > 96 ? 96 : y + 3;
                uint4 acc = Gh[ym3];
                for (int yy = ym3 + 1; yy <= yp3; yy++) acc = bor(acc, Gh[yy]);
                acc.x &= Gm[y].x; acc.y &= Gm[y].y; acc.z &= Gm[y].z; acc.w &= Gm[y].w;
                if (y == 48 && sv > 0.f) acc.y |= (1u << 16);
                Gs[y] = acc;
            }
            __syncthreads();
        }

        // ---- fused BCE: mantissa-product + exponent accumulation ----
        int ylo = 3 > -gr0 ? 3 : -gr0;
        int yhi = 93 < 255 - gr0 ? 93 : 255 - gr0;
        int xlo = 3 > -gc0 ? 3 : -gc0;
        int xhi = 93 < 255 - gc0 ? 93 : 255 - gc0;
        int nrows2 = yhi - ylo + 1;
        float pm = 1.0f;
        int   pe = 0;
        for (unsigned u = tid; u < (unsigned)nrows2 * 13u; u += 1024) {
            unsigned yy = u / 13u;
            unsigned g = u - yy * 13u;
            int y = ylo + (int)yy;
            int C = (int)(g << 3);
            if (C + 7 < xlo || C > xhi) continue;
            uint4 pv8 = *(const uint4*)(A + y * PH + PADC + C);
            uint4 gw = Gs[y];
            float2 f[4];
            f[0] = __half22float2(*(__half2*)&pv8.x);
            f[1] = __half22float2(*(__half2*)&pv8.y);
            f[2] = __half22float2(*(__half2*)&pv8.z);
            f[3] = __half22float2(*(__half2*)&pv8.w);
            const float* fv = (const float*)f;
            #pragma unroll
            for (int k = 0; k < 8; k++) {
                int x = C + k;
                if (x >= xlo && x <= xhi) {
                    float p = fminf(fmaxf(fv[k], 1e-7f), 1.0f - 1e-7f);
                    int ws = x >> 5;
                    unsigned word = ws == 0 ? gw.x : ws == 1 ? gw.y : ws == 2 ? gw.z : gw.w;
                    float t = ((word >> (x & 31)) & 1u) ? p : (1.0f - p);
                    pm *= t;
                }
                if ((k & 3) == 3) {
                    int bi = __float_as_int(pm);
                    pe += (bi >> 23) - 127;
                    pm = __int_as_float((bi & 0x007fffff) | 0x3f800000);
                }
            }
        }
        float local = -(__logf(pm) + (float)pe * 0.69314718056f);

        #pragma unroll
        for (int off = 16; off; off >>= 1)
            local += __shfl_down_sync(0xffffffffu, local, off);
        if ((tid & 31) == 0) wpart[tid >> 5] = local;
        __syncthreads();
        if (tid == 0) {
            float s = 0.f;
            #pragma unroll
            for (int k = 0; k < 32; k++) s += wpart[k];
            float area = (float)((yhi - ylo + 1) * (xhi - xlo + 1));
            s += (65536.0f - area) * c0log;
            g_partial[ch] = s;
        }
    }

    // ---- last-block finalize ----
    if (tid == 0) {
        __threadfence();
        int old = atomicAdd(&g_done, 1);
        s_last = (old == NCH - 1);
    }
    __syncthreads();
    if (s_last && tid < 32) {
        float v = g_partial[tid] + g_partial[tid + 32] +
                  g_partial[tid + 64] + g_partial[tid + 96];
        #pragma unroll
        for (int off = 16; off; off >>= 1)
            v += __shfl_down_sync(0xffffffffu, v, off);
        if (tid == 0) {
            out[0] = 0.5f * v / 8388608.0f;
            g_done = 0;
        }
    }
}

extern "C" void kernel_launch(void* const* d_in, const int* in_sizes, int n_in,
                              void* d_out, int out_size) {
    const float* cls = (const float*)d_in[0];
    const int* lab   = (const int*)d_in[1];
    const float4* seeds = (const float4*)d_in[2];

    cudaFuncSetAttribute(k_flood, cudaFuncAttributeMaxDynamicSharedMemorySize, SMEM_BYTES);

    k_prep<<<2048, 256>>>(cls, lab, seeds);

    // PDL launch of k_flood: CTAs may start early, do pre-dependency smem zeroing,
    // then griddepcontrol.wait for k_prep's results.
    cudaLaunchConfig_t cfg = {};
    cfg.gridDim = dim3(128, 1, 1);
    cfg.blockDim = dim3(1024, 1, 1);
    cfg.dynamicSmemBytes = SMEM_BYTES;
    cfg.stream = 0;
    cudaLaunchAttribute attr[1];
    attr[0].id = cudaLaunchAttributeProgrammaticStreamSerialization;
    attr[0].val.programmaticStreamSerializationAllowed = 1;
    cfg.attrs = attr;
    cfg.numAttrs = 1;
    float* outp = (float*)d_out;
    cudaError_t e = cudaLaunchKernelEx(&cfg, k_flood, outp);
    if (e != cudaSuccess) {
        k_flood<<<128, 1024, SMEM_BYTES>>>(outp);
    }
}